// round 1
// baseline (speedup 1.0000x reference)
#include <cuda_runtime.h>
#include <cstdint>

#define NB      4
#define NUM_VN  65536
#define NUM_CN  32768
#define DD      32
#define NE      262144
#define HID     40
#define MSG     20

// Message scratch: [side][b][cn][MSG]  = 2*4*32768*20 floats = 21 MB
__device__ float g_msg[2u * NB * NUM_CN * MSG];

__device__ __forceinline__ void red_add_v4(float* p, float a, float b, float c, float d) {
    asm volatile("red.global.add.v4.f32 [%0], {%1,%2,%3,%4};"
                 :: "l"(p), "f"(a), "f"(b), "f"(c), "f"(d) : "memory");
}

__global__ void __launch_bounds__(256) zero_msg_kernel() {
    float4* p = reinterpret_cast<float4*>(g_msg);
    const int n = (2 * NB * NUM_CN * MSG) / 4;
    for (int i = blockIdx.x * blockDim.x + threadIdx.x; i < n; i += gridDim.x * blockDim.x)
        p[i] = make_float4(0.f, 0.f, 0.f, 0.f);
}

// ---------------------------------------------------------------------------
// Edge kernel: one thread per edge, loops over batches.
// feat = [h_from[fi] (32), h_to[ti] (32)];  hid = relu(feat @ Wm1);  msg = hid @ Wm2
// scatter msg into g_msg[side][b][ti][:] via vectorized RED.
// ---------------------------------------------------------------------------
__global__ void __launch_bounds__(128) edge_kernel(
    const float* __restrict__ h_from,
    const float* __restrict__ h_to_x, const float* __restrict__ h_to_z,
    const int* __restrict__ fx, const int* __restrict__ tx,
    const int* __restrict__ fz, const int* __restrict__ tz,
    const float* __restrict__ Wm1x, const float* __restrict__ Wm2x,
    const float* __restrict__ Wm1z, const float* __restrict__ Wm2z)
{
    const int side = blockIdx.y;
    const float* __restrict__ h_to = side ? h_to_z : h_to_x;
    const int* __restrict__ fi_arr = side ? fz : fx;
    const int* __restrict__ ti_arr = side ? tz : tx;
    const float* __restrict__ W1 = side ? Wm1z : Wm1x;   // [64, 40]
    const float* __restrict__ W2 = side ? Wm2z : Wm2x;   // [40, 20]

    __shared__ float w1s[64 * HID];
    __shared__ float w2s[HID * MSG];
    for (int i = threadIdx.x; i < 64 * HID; i += 128) w1s[i] = W1[i];
    for (int i = threadIdx.x; i < HID * MSG; i += 128) w2s[i] = W2[i];
    __syncthreads();

    const int e = blockIdx.x * 128 + threadIdx.x;
    const int fi = fi_arr[e];
    const int ti = ti_arr[e];

#pragma unroll 1
    for (int b = 0; b < NB; ++b) {
        float hid[HID];
#pragma unroll
        for (int j = 0; j < HID; ++j) hid[j] = 0.f;

        // ---- first 32 features: h_from[b, fi, :] ----
        {
            const float4* src = reinterpret_cast<const float4*>(
                h_from + ((size_t)b * NUM_VN + fi) * DD);
#pragma unroll 2
            for (int i = 0; i < 8; ++i) {
                float4 v = src[i];
                const float* wr = &w1s[i * 4 * HID];
#pragma unroll
                for (int j = 0; j < HID; ++j) hid[j] = fmaf(v.x, wr[j], hid[j]);
#pragma unroll
                for (int j = 0; j < HID; ++j) hid[j] = fmaf(v.y, wr[HID + j], hid[j]);
#pragma unroll
                for (int j = 0; j < HID; ++j) hid[j] = fmaf(v.z, wr[2 * HID + j], hid[j]);
#pragma unroll
                for (int j = 0; j < HID; ++j) hid[j] = fmaf(v.w, wr[3 * HID + j], hid[j]);
            }
        }
        // ---- next 32 features: h_to[b, ti, :] ----
        {
            const float4* src = reinterpret_cast<const float4*>(
                h_to + ((size_t)b * NUM_CN + ti) * DD);
#pragma unroll 2
            for (int i = 0; i < 8; ++i) {
                float4 v = src[i];
                const float* wr = &w1s[(32 + i * 4) * HID];
#pragma unroll
                for (int j = 0; j < HID; ++j) hid[j] = fmaf(v.x, wr[j], hid[j]);
#pragma unroll
                for (int j = 0; j < HID; ++j) hid[j] = fmaf(v.y, wr[HID + j], hid[j]);
#pragma unroll
                for (int j = 0; j < HID; ++j) hid[j] = fmaf(v.z, wr[2 * HID + j], hid[j]);
#pragma unroll
                for (int j = 0; j < HID; ++j) hid[j] = fmaf(v.w, wr[3 * HID + j], hid[j]);
            }
        }

        // ---- msg = relu(hid) @ W2 ----
        float msg[MSG];
#pragma unroll
        for (int o = 0; o < MSG; ++o) msg[o] = 0.f;
#pragma unroll 4
        for (int j = 0; j < HID; ++j) {
            float h = fmaxf(hid[j], 0.f);
            const float* wr = &w2s[j * MSG];
#pragma unroll
            for (int o = 0; o < MSG; ++o) msg[o] = fmaf(h, wr[o], msg[o]);
        }

        // ---- scatter-add onto receiving check node ----
        float* dst = g_msg + (((size_t)side * NB + b) * NUM_CN + ti) * MSG;
#pragma unroll
        for (int i = 0; i < 5; ++i)
            red_add_v4(dst + 4 * i, msg[4 * i], msg[4 * i + 1], msg[4 * i + 2], msg[4 * i + 3]);
    }
}

// ---------------------------------------------------------------------------
// Node kernel: one thread per check node per batch per side.
// emb_in = [m (20), h_to (32), logit (1)];  out = relu(emb_in @ We1) @ We2
// ---------------------------------------------------------------------------
__global__ void __launch_bounds__(256) node_kernel(
    const float* __restrict__ h_to_x, const float* __restrict__ h_to_z,
    const float* __restrict__ lx, const float* __restrict__ lz,
    const float* __restrict__ We1x, const float* __restrict__ We2x,
    const float* __restrict__ We1z, const float* __restrict__ We2z,
    float* __restrict__ out)
{
    const int side = blockIdx.z;
    const int b = blockIdx.y;
    const float* __restrict__ h_to  = side ? h_to_z : h_to_x;
    const float* __restrict__ logit = side ? lz : lx;
    const float* __restrict__ W1 = side ? We1z : We1x;   // [53, 40]
    const float* __restrict__ W2 = side ? We2z : We2x;   // [40, 32]

    __shared__ float w1s[53 * HID];
    __shared__ float w2s[HID * DD];
    for (int i = threadIdx.x; i < 53 * HID; i += 256) w1s[i] = W1[i];
    for (int i = threadIdx.x; i < HID * DD; i += 256) w2s[i] = W2[i];
    __syncthreads();

    const int n = blockIdx.x * 256 + threadIdx.x;

    float hid[HID];
#pragma unroll
    for (int j = 0; j < HID; ++j) hid[j] = 0.f;

    // m part (features 0..19)
    const float* mrow = g_msg + (((size_t)side * NB + b) * NUM_CN + n) * MSG;
#pragma unroll
    for (int i = 0; i < 5; ++i) {
        float4 v = *reinterpret_cast<const float4*>(mrow + 4 * i);
        const float* wr = &w1s[i * 4 * HID];
#pragma unroll
        for (int j = 0; j < HID; ++j) hid[j] = fmaf(v.x, wr[j], hid[j]);
#pragma unroll
        for (int j = 0; j < HID; ++j) hid[j] = fmaf(v.y, wr[HID + j], hid[j]);
#pragma unroll
        for (int j = 0; j < HID; ++j) hid[j] = fmaf(v.z, wr[2 * HID + j], hid[j]);
#pragma unroll
        for (int j = 0; j < HID; ++j) hid[j] = fmaf(v.w, wr[3 * HID + j], hid[j]);
    }
    // h_to part (features 20..51)
    const float4* hrow = reinterpret_cast<const float4*>(h_to + ((size_t)b * NUM_CN + n) * DD);
#pragma unroll 2
    for (int i = 0; i < 8; ++i) {
        float4 v = hrow[i];
        const float* wr = &w1s[(MSG + i * 4) * HID];
#pragma unroll
        for (int j = 0; j < HID; ++j) hid[j] = fmaf(v.x, wr[j], hid[j]);
#pragma unroll
        for (int j = 0; j < HID; ++j) hid[j] = fmaf(v.y, wr[HID + j], hid[j]);
#pragma unroll
        for (int j = 0; j < HID; ++j) hid[j] = fmaf(v.z, wr[2 * HID + j], hid[j]);
#pragma unroll
        for (int j = 0; j < HID; ++j) hid[j] = fmaf(v.w, wr[3 * HID + j], hid[j]);
    }
    // logit (feature 52)
    {
        float lg = logit[(size_t)b * NUM_CN + n];
        const float* wr = &w1s[52 * HID];
#pragma unroll
        for (int j = 0; j < HID; ++j) hid[j] = fmaf(lg, wr[j], hid[j]);
    }

    float acc[DD];
#pragma unroll
    for (int o = 0; o < DD; ++o) acc[o] = 0.f;
#pragma unroll 4
    for (int j = 0; j < HID; ++j) {
        float h = fmaxf(hid[j], 0.f);
        const float* wr = &w2s[j * DD];
#pragma unroll
        for (int o = 0; o < DD; ++o) acc[o] = fmaf(h, wr[o], acc[o]);
    }

    float* dst = out + (((size_t)side * NB + b) * NUM_CN + n) * DD;
#pragma unroll
    for (int i = 0; i < 8; ++i)
        *reinterpret_cast<float4*>(dst + 4 * i) =
            make_float4(acc[4 * i], acc[4 * i + 1], acc[4 * i + 2], acc[4 * i + 3]);
}

extern "C" void kernel_launch(void* const* d_in, const int* in_sizes, int n_in,
                              void* d_out, int out_size)
{
    const float* h_from   = (const float*)d_in[0];
    const float* h_to_x   = (const float*)d_in[1];
    const float* h_to_z   = (const float*)d_in[2];
    const float* hx_logit = (const float*)d_in[3];
    const float* hz_logit = (const float*)d_in[4];
    const int*   fx       = (const int*)d_in[5];
    const int*   tx       = (const int*)d_in[6];
    const int*   fz       = (const int*)d_in[7];
    const int*   tz       = (const int*)d_in[8];
    const float* Wm1x     = (const float*)d_in[9];
    const float* Wm2x     = (const float*)d_in[10];
    const float* Wm1z     = (const float*)d_in[11];
    const float* Wm2z     = (const float*)d_in[12];
    const float* We1x     = (const float*)d_in[13];
    const float* We2x     = (const float*)d_in[14];
    const float* We1z     = (const float*)d_in[15];
    const float* We2z     = (const float*)d_in[16];
    float* out = (float*)d_out;

    zero_msg_kernel<<<512, 256>>>();

    dim3 egrid(NE / 128, 2);
    edge_kernel<<<egrid, 128>>>(h_from, h_to_x, h_to_z,
                                fx, tx, fz, tz,
                                Wm1x, Wm2x, Wm1z, Wm2z);

    dim3 ngrid(NUM_CN / 256, NB, 2);
    node_kernel<<<ngrid, 256>>>(h_to_x, h_to_z, hx_logit, hz_logit,
                                We1x, We2x, We1z, We2z, out);
}

// round 2
// speedup vs baseline: 1.5929x; 1.5929x over previous
#include <cuda_runtime.h>
#include <cstdint>

#define NB      4
#define NUM_VN  65536
#define NUM_CN  32768
#define DD      32
#define NE      262144
#define HID     40
#define MSG     20

// Scratch:
// projected from-node features per side: [2][NB][NUM_VN][HID]  (84 MB)
__device__ float g_hidF[2u * NB * NUM_VN * HID];
// projected to-node features per side:   [2][NB][NUM_CN][HID]  (42 MB)
__device__ float g_hidT[2u * NB * NUM_CN * HID];
// message accumulators: [2][NB][NUM_CN][MSG]                   (21 MB)
__device__ float g_msg[2u * NB * NUM_CN * MSG];

__device__ __forceinline__ void red_add_v4(float* p, float a, float b, float c, float d) {
    asm volatile("red.global.add.v4.f32 [%0], {%1,%2,%3,%4};"
                 :: "l"(p), "f"(a), "f"(b), "f"(c), "f"(d) : "memory");
}

__global__ void __launch_bounds__(256) zero_msg_kernel() {
    float4* p = reinterpret_cast<float4*>(g_msg);
    const int n = (2 * NB * NUM_CN * MSG) / 4;
    for (int i = blockIdx.x * blockDim.x + threadIdx.x; i < n; i += gridDim.x * blockDim.x)
        p[i] = make_float4(0.f, 0.f, 0.f, 0.f);
}

// ---------------------------------------------------------------------------
// Projection kernel: dst[b, n, :] = src[b, n, :] @ W1[w_row_off : w_row_off+32, :]
// One thread per node; grid.y = batch. Weights staged in smem (broadcast LDS).
// ---------------------------------------------------------------------------
__global__ void __launch_bounds__(256) proj_kernel(
    const float* __restrict__ src,   // [NB, nnodes, DD]
    const float* __restrict__ W1,    // [64, HID], rows w_row_off..+31 used
    int w_row_off, int nnodes,
    float* __restrict__ dst)         // [NB, nnodes, HID]
{
    __shared__ float w1s[DD * HID];  // 32 x 40
    for (int i = threadIdx.x; i < DD * HID; i += 256)
        w1s[i] = W1[w_row_off * HID + i];
    __syncthreads();

    const int n = blockIdx.x * 256 + threadIdx.x;
    const int b = blockIdx.y;

    float acc[HID];
#pragma unroll
    for (int j = 0; j < HID; ++j) acc[j] = 0.f;

    const float4* row = reinterpret_cast<const float4*>(
        src + ((size_t)b * nnodes + n) * DD);
#pragma unroll
    for (int i = 0; i < 8; ++i) {
        float4 v = row[i];
        const float* wr = &w1s[i * 4 * HID];
#pragma unroll
        for (int j = 0; j < HID; ++j) acc[j] = fmaf(v.x, wr[j], acc[j]);
#pragma unroll
        for (int j = 0; j < HID; ++j) acc[j] = fmaf(v.y, wr[HID + j], acc[j]);
#pragma unroll
        for (int j = 0; j < HID; ++j) acc[j] = fmaf(v.z, wr[2 * HID + j], acc[j]);
#pragma unroll
        for (int j = 0; j < HID; ++j) acc[j] = fmaf(v.w, wr[3 * HID + j], acc[j]);
    }

    float* d = dst + ((size_t)b * nnodes + n) * HID;
#pragma unroll
    for (int i = 0; i < 10; ++i)
        *reinterpret_cast<float4*>(d + 4 * i) =
            make_float4(acc[4 * i], acc[4 * i + 1], acc[4 * i + 2], acc[4 * i + 3]);
}

// ---------------------------------------------------------------------------
// Edge kernel: one thread per edge, loops over batches.
// hid = relu(hidF[b,fi] + hidT[b,ti]);  msg = hid @ W2;  RED-scatter to g_msg.
// ---------------------------------------------------------------------------
__global__ void __launch_bounds__(256) edge_kernel(
    const int* __restrict__ fx, const int* __restrict__ tx,
    const int* __restrict__ fz, const int* __restrict__ tz,
    const float* __restrict__ Wm2x, const float* __restrict__ Wm2z)
{
    const int side = blockIdx.y;
    const int* __restrict__ fi_arr = side ? fz : fx;
    const int* __restrict__ ti_arr = side ? tz : tx;
    const float* __restrict__ W2 = side ? Wm2z : Wm2x;   // [HID, MSG]

    __shared__ float w2s[HID * MSG];
    for (int i = threadIdx.x; i < HID * MSG; i += 256) w2s[i] = W2[i];
    __syncthreads();

    const int e = blockIdx.x * 256 + threadIdx.x;
    const int fi = fi_arr[e];
    const int ti = ti_arr[e];

    const float* hidF = g_hidF + (size_t)side * NB * NUM_VN * HID;
    const float* hidT = g_hidT + (size_t)side * NB * NUM_CN * HID;

#pragma unroll 1
    for (int b = 0; b < NB; ++b) {
        const float4* F = reinterpret_cast<const float4*>(
            hidF + ((size_t)b * NUM_VN + fi) * HID);
        const float4* T = reinterpret_cast<const float4*>(
            hidT + ((size_t)b * NUM_CN + ti) * HID);

        float msg[MSG];
#pragma unroll
        for (int o = 0; o < MSG; ++o) msg[o] = 0.f;

#pragma unroll
        for (int g = 0; g < 10; ++g) {
            float4 fv = F[g];
            float4 tv = T[g];
            float h0 = fmaxf(fv.x + tv.x, 0.f);
            float h1 = fmaxf(fv.y + tv.y, 0.f);
            float h2 = fmaxf(fv.z + tv.z, 0.f);
            float h3 = fmaxf(fv.w + tv.w, 0.f);
            const float* wr = &w2s[(4 * g) * MSG];
#pragma unroll
            for (int o = 0; o < MSG; ++o) msg[o] = fmaf(h0, wr[o], msg[o]);
#pragma unroll
            for (int o = 0; o < MSG; ++o) msg[o] = fmaf(h1, wr[MSG + o], msg[o]);
#pragma unroll
            for (int o = 0; o < MSG; ++o) msg[o] = fmaf(h2, wr[2 * MSG + o], msg[o]);
#pragma unroll
            for (int o = 0; o < MSG; ++o) msg[o] = fmaf(h3, wr[3 * MSG + o], msg[o]);
        }

        float* dst = g_msg + (((size_t)side * NB + b) * NUM_CN + ti) * MSG;
#pragma unroll
        for (int i = 0; i < 5; ++i)
            red_add_v4(dst + 4 * i, msg[4 * i], msg[4 * i + 1], msg[4 * i + 2], msg[4 * i + 3]);
    }
}

// ---------------------------------------------------------------------------
// Node kernel: one thread per (check node, batch, side).
// emb_in = [m (20), h_to (32), logit (1)];  out = relu(emb_in @ We1) @ We2
// ---------------------------------------------------------------------------
__global__ void __launch_bounds__(256) node_kernel(
    const float* __restrict__ h_to_x, const float* __restrict__ h_to_z,
    const float* __restrict__ lx, const float* __restrict__ lz,
    const float* __restrict__ We1x, const float* __restrict__ We2x,
    const float* __restrict__ We1z, const float* __restrict__ We2z,
    float* __restrict__ out)
{
    const int side = blockIdx.z;
    const int b = blockIdx.y;
    const float* __restrict__ h_to  = side ? h_to_z : h_to_x;
    const float* __restrict__ logit = side ? lz : lx;
    const float* __restrict__ W1 = side ? We1z : We1x;   // [53, 40]
    const float* __restrict__ W2 = side ? We2z : We2x;   // [40, 32]

    __shared__ float w1s[53 * HID];
    __shared__ float w2s[HID * DD];
    for (int i = threadIdx.x; i < 53 * HID; i += 256) w1s[i] = W1[i];
    for (int i = threadIdx.x; i < HID * DD; i += 256) w2s[i] = W2[i];
    __syncthreads();

    const int n = blockIdx.x * 256 + threadIdx.x;

    float hid[HID];
#pragma unroll
    for (int j = 0; j < HID; ++j) hid[j] = 0.f;

    // m part (features 0..19)
    const float* mrow = g_msg + (((size_t)side * NB + b) * NUM_CN + n) * MSG;
#pragma unroll
    for (int i = 0; i < 5; ++i) {
        float4 v = *reinterpret_cast<const float4*>(mrow + 4 * i);
        const float* wr = &w1s[i * 4 * HID];
#pragma unroll
        for (int j = 0; j < HID; ++j) hid[j] = fmaf(v.x, wr[j], hid[j]);
#pragma unroll
        for (int j = 0; j < HID; ++j) hid[j] = fmaf(v.y, wr[HID + j], hid[j]);
#pragma unroll
        for (int j = 0; j < HID; ++j) hid[j] = fmaf(v.z, wr[2 * HID + j], hid[j]);
#pragma unroll
        for (int j = 0; j < HID; ++j) hid[j] = fmaf(v.w, wr[3 * HID + j], hid[j]);
    }
    // h_to part (features 20..51)
    const float4* hrow = reinterpret_cast<const float4*>(h_to + ((size_t)b * NUM_CN + n) * DD);
#pragma unroll 2
    for (int i = 0; i < 8; ++i) {
        float4 v = hrow[i];
        const float* wr = &w1s[(MSG + i * 4) * HID];
#pragma unroll
        for (int j = 0; j < HID; ++j) hid[j] = fmaf(v.x, wr[j], hid[j]);
#pragma unroll
        for (int j = 0; j < HID; ++j) hid[j] = fmaf(v.y, wr[HID + j], hid[j]);
#pragma unroll
        for (int j = 0; j < HID; ++j) hid[j] = fmaf(v.z, wr[2 * HID + j], hid[j]);
#pragma unroll
        for (int j = 0; j < HID; ++j) hid[j] = fmaf(v.w, wr[3 * HID + j], hid[j]);
    }
    // logit (feature 52)
    {
        float lg = logit[(size_t)b * NUM_CN + n];
        const float* wr = &w1s[52 * HID];
#pragma unroll
        for (int j = 0; j < HID; ++j) hid[j] = fmaf(lg, wr[j], hid[j]);
    }

    float acc[DD];
#pragma unroll
    for (int o = 0; o < DD; ++o) acc[o] = 0.f;
#pragma unroll 4
    for (int j = 0; j < HID; ++j) {
        float h = fmaxf(hid[j], 0.f);
        const float* wr = &w2s[j * DD];
#pragma unroll
        for (int o = 0; o < DD; ++o) acc[o] = fmaf(h, wr[o], acc[o]);
    }

    float* dst = out + (((size_t)side * NB + b) * NUM_CN + n) * DD;
#pragma unroll
    for (int i = 0; i < 8; ++i)
        *reinterpret_cast<float4*>(dst + 4 * i) =
            make_float4(acc[4 * i], acc[4 * i + 1], acc[4 * i + 2], acc[4 * i + 3]);
}

extern "C" void kernel_launch(void* const* d_in, const int* in_sizes, int n_in,
                              void* d_out, int out_size)
{
    const float* h_from   = (const float*)d_in[0];
    const float* h_to_x   = (const float*)d_in[1];
    const float* h_to_z   = (const float*)d_in[2];
    const float* hx_logit = (const float*)d_in[3];
    const float* hz_logit = (const float*)d_in[4];
    const int*   fx       = (const int*)d_in[5];
    const int*   tx       = (const int*)d_in[6];
    const int*   fz       = (const int*)d_in[7];
    const int*   tz       = (const int*)d_in[8];
    const float* Wm1x     = (const float*)d_in[9];
    const float* Wm2x     = (const float*)d_in[10];
    const float* Wm1z     = (const float*)d_in[11];
    const float* Wm2z     = (const float*)d_in[12];
    const float* We1x     = (const float*)d_in[13];
    const float* We2x     = (const float*)d_in[14];
    const float* We1z     = (const float*)d_in[15];
    const float* We2z     = (const float*)d_in[16];
    float* out = (float*)d_out;

    float* hidFx; float* hidFz; float* hidTx; float* hidTz; float* msgp;
    cudaGetSymbolAddress((void**)&hidFx, g_hidF);
    hidFz = hidFx + (size_t)NB * NUM_VN * HID;
    cudaGetSymbolAddress((void**)&hidTx, g_hidT);
    hidTz = hidTx + (size_t)NB * NUM_CN * HID;

    zero_msg_kernel<<<512, 256>>>();

    // Node-feature projections (hid contributions independent of edges)
    dim3 fgrid(NUM_VN / 256, NB);
    proj_kernel<<<fgrid, 256>>>(h_from, Wm1x, 0, NUM_VN, hidFx);
    proj_kernel<<<fgrid, 256>>>(h_from, Wm1z, 0, NUM_VN, hidFz);
    dim3 tgrid(NUM_CN / 256, NB);
    proj_kernel<<<tgrid, 256>>>(h_to_x, Wm1x, DD, NUM_CN, hidTx);
    proj_kernel<<<tgrid, 256>>>(h_to_z, Wm1z, DD, NUM_CN, hidTz);

    // Per-edge message + scatter
    dim3 egrid(NE / 256, 2);
    edge_kernel<<<egrid, 256>>>(fx, tx, fz, tz, Wm2x, Wm2z);

    // Node update MLP
    dim3 ngrid(NUM_CN / 256, NB, 2);
    node_kernel<<<ngrid, 256>>>(h_to_x, h_to_z, hx_logit, hz_logit,
                                We1x, We2x, We1z, We2z, out);
}

// round 3
// speedup vs baseline: 1.9812x; 1.2438x over previous
#include <cuda_runtime.h>
#include <cstdint>

#define NB      4
#define NUM_VN  65536
#define NUM_CN  32768
#define DD      32
#define NE      262144
#define HID     40
#define MSG     20

// Scratch
__device__ float g_hidF[2u * NB * NUM_VN * HID];   // 84 MB: per-side from-node projections
__device__ int   g_cnt[2 * NUM_CN];
__device__ int   g_cur[2 * NUM_CN];
__device__ int   g_rowptr[2 * (NUM_CN + 1)];
__device__ int   g_src[2 * NE];                    // from-indices sorted by destination
__device__ float g_wf[2 * HID * HID];              // Wf = Wm2 @ We1[0:MSG]

// ---------------------------------------------------------------------------
__global__ void __launch_bounds__(256) zero_cnt_kernel() {
    int i = blockIdx.x * 256 + threadIdx.x;
    if (i < 2 * NUM_CN) { g_cnt[i] = 0; }
}

__global__ void __launch_bounds__(256) hist_kernel(
    const int* __restrict__ tx, const int* __restrict__ tz)
{
    const int side = blockIdx.y;
    const int* ti_arr = side ? tz : tx;
    int e = blockIdx.x * 256 + threadIdx.x;
    atomicAdd(&g_cnt[side * NUM_CN + ti_arr[e]], 1);
}

// one block (1024 threads) per side; each thread scans 32 entries
__global__ void __launch_bounds__(1024) scan_kernel() {
    const int side = blockIdx.x;
    const int t = threadIdx.x;
    __shared__ int part[1024];

    const int n0 = t * 32;
    int tsum = 0;
    int loc[32];
#pragma unroll
    for (int i = 0; i < 32; ++i) { loc[i] = g_cnt[side * NUM_CN + n0 + i]; tsum += loc[i]; }
    part[t] = tsum;
    __syncthreads();
#pragma unroll
    for (int off = 1; off < 1024; off <<= 1) {
        int v = (t >= off) ? part[t - off] : 0;
        __syncthreads();
        part[t] += v;
        __syncthreads();
    }
    int base = part[t] - tsum;   // exclusive prefix of this thread's chunk
#pragma unroll
    for (int i = 0; i < 32; ++i) {
        g_rowptr[side * (NUM_CN + 1) + n0 + i] = base;
        g_cur[side * NUM_CN + n0 + i] = base;
        base += loc[i];
    }
    if (t == 1023) g_rowptr[side * (NUM_CN + 1) + NUM_CN] = NE;
}

__global__ void __launch_bounds__(256) fill_kernel(
    const int* __restrict__ fx, const int* __restrict__ tx,
    const int* __restrict__ fz, const int* __restrict__ tz)
{
    const int side = blockIdx.y;
    const int* fi_arr = side ? fz : fx;
    const int* ti_arr = side ? tz : tx;
    int e = blockIdx.x * 256 + threadIdx.x;
    int ti = ti_arr[e];
    int pos = atomicAdd(&g_cur[side * NUM_CN + ti], 1);
    g_src[side * NE + pos] = fi_arr[e];
}

// Wf[i][j] = sum_k Wm2[i][k] * We1[k][j],  i<HID, k<MSG, j<HID
__global__ void __launch_bounds__(256) wf_build_kernel(
    const float* __restrict__ Wm2x, const float* __restrict__ We1x,
    const float* __restrict__ Wm2z, const float* __restrict__ We1z)
{
    const int side = blockIdx.x;
    const float* W2 = side ? Wm2z : Wm2x;
    const float* W1 = side ? We1z : We1x;
    for (int idx = threadIdx.x; idx < HID * HID; idx += 256) {
        int i = idx / HID, j = idx % HID;
        float a = 0.f;
#pragma unroll
        for (int k = 0; k < MSG; ++k) a = fmaf(W2[i * MSG + k], W1[k * HID + j], a);
        g_wf[side * HID * HID + idx] = a;
    }
}

// ---------------------------------------------------------------------------
// From-node projection: hidF[side][b][vn][:] = h_from[b,vn,:] @ Wm1_side[0:32,:]
// 2 nodes per thread (n and n + NUM_VN/2) so each weight LDS feeds 2 FMAs.
// ---------------------------------------------------------------------------
__global__ void __launch_bounds__(128) proj_from_kernel(
    const float* __restrict__ h_from,
    const float* __restrict__ Wm1x, const float* __restrict__ Wm1z)
{
    const int side = blockIdx.z;
    const int b = blockIdx.y;
    const float* __restrict__ W1 = side ? Wm1z : Wm1x;

    __shared__ float w1s[DD * HID];
    for (int i = threadIdx.x; i < DD * HID; i += 128) w1s[i] = W1[i];
    __syncthreads();

    const int n0 = blockIdx.x * 128 + threadIdx.x;
    const int n1 = n0 + NUM_VN / 2;

    float a0[HID], a1[HID];
#pragma unroll
    for (int j = 0; j < HID; ++j) { a0[j] = 0.f; a1[j] = 0.f; }

    const float4* r0 = reinterpret_cast<const float4*>(h_from + ((size_t)b * NUM_VN + n0) * DD);
    const float4* r1 = reinterpret_cast<const float4*>(h_from + ((size_t)b * NUM_VN + n1) * DD);
#pragma unroll
    for (int i = 0; i < 8; ++i) {
        float4 u = r0[i];
        float4 v = r1[i];
        const float* wr = &w1s[i * 4 * HID];
#pragma unroll
        for (int j = 0; j < HID; ++j) { float w = wr[j];            a0[j] = fmaf(u.x, w, a0[j]); a1[j] = fmaf(v.x, w, a1[j]); }
#pragma unroll
        for (int j = 0; j < HID; ++j) { float w = wr[HID + j];      a0[j] = fmaf(u.y, w, a0[j]); a1[j] = fmaf(v.y, w, a1[j]); }
#pragma unroll
        for (int j = 0; j < HID; ++j) { float w = wr[2 * HID + j];  a0[j] = fmaf(u.z, w, a0[j]); a1[j] = fmaf(v.z, w, a1[j]); }
#pragma unroll
        for (int j = 0; j < HID; ++j) { float w = wr[3 * HID + j];  a0[j] = fmaf(u.w, w, a0[j]); a1[j] = fmaf(v.w, w, a1[j]); }
    }

    float* base = g_hidF + ((size_t)side * NB + b) * NUM_VN * HID;
    float* d0 = base + (size_t)n0 * HID;
    float* d1 = base + (size_t)n1 * HID;
#pragma unroll
    for (int i = 0; i < 10; ++i) {
        *reinterpret_cast<float4*>(d0 + 4 * i) = make_float4(a0[4*i], a0[4*i+1], a0[4*i+2], a0[4*i+3]);
        *reinterpret_cast<float4*>(d1 + 4 * i) = make_float4(a1[4*i], a1[4*i+1], a1[4*i+2], a1[4*i+3]);
    }
}

// ---------------------------------------------------------------------------
// Fused node kernel: per (cn, b, side)
//   t   = h_to_row @ Wm1_side[32:64]                    (edge-invariant projection)
//   s   = sum over incoming edges of relu(hidF[fi] + t)
//   hid = s @ Wf + h_to_row @ We1[20:52] + logit * We1[52]
//   out = relu(hid) @ We2
// ---------------------------------------------------------------------------
__global__ void __launch_bounds__(128) fused_node_kernel(
    const float* __restrict__ h_to_x, const float* __restrict__ h_to_z,
    const float* __restrict__ lx, const float* __restrict__ lz,
    const float* __restrict__ Wm1x, const float* __restrict__ Wm1z,
    const float* __restrict__ We1x, const float* __restrict__ We1z,
    const float* __restrict__ We2x, const float* __restrict__ We2z,
    float* __restrict__ out)
{
    const int side = blockIdx.z;
    const int b = blockIdx.y;
    const float* __restrict__ h_to  = side ? h_to_z : h_to_x;
    const float* __restrict__ logit = side ? lz : lx;
    const float* __restrict__ Wm1 = side ? Wm1z : Wm1x;
    const float* __restrict__ We1 = side ? We1z : We1x;
    const float* __restrict__ We2 = side ? We2z : We2x;

    __shared__ float wm1s[DD * HID];    // Wm1 rows 32..63
    __shared__ float wfs[HID * HID];    // Wf
    __shared__ float we1h[DD * HID];    // We1 rows 20..51
    __shared__ float we1l[HID];         // We1 row 52
    __shared__ float we2s[HID * DD];

    for (int i = threadIdx.x; i < DD * HID; i += 128) wm1s[i] = Wm1[DD * HID + i];
    for (int i = threadIdx.x; i < HID * HID; i += 128) wfs[i] = g_wf[side * HID * HID + i];
    for (int i = threadIdx.x; i < DD * HID; i += 128) we1h[i] = We1[MSG * HID + i];
    for (int i = threadIdx.x; i < HID; i += 128) we1l[i] = We1[52 * HID + i];
    for (int i = threadIdx.x; i < HID * DD; i += 128) we2s[i] = We2[i];
    __syncthreads();

    const int n = blockIdx.x * 128 + threadIdx.x;
    const float4* row = reinterpret_cast<const float4*>(h_to + ((size_t)b * NUM_CN + n) * DD);

    // ---- t = h_to_row @ Wm1[32:64] ----
    float t[HID];
#pragma unroll
    for (int j = 0; j < HID; ++j) t[j] = 0.f;
#pragma unroll
    for (int i = 0; i < 8; ++i) {
        float4 v = row[i];
        const float* wr = &wm1s[i * 4 * HID];
#pragma unroll
        for (int j = 0; j < HID; ++j) t[j] = fmaf(v.x, wr[j], t[j]);
#pragma unroll
        for (int j = 0; j < HID; ++j) t[j] = fmaf(v.y, wr[HID + j], t[j]);
#pragma unroll
        for (int j = 0; j < HID; ++j) t[j] = fmaf(v.z, wr[2 * HID + j], t[j]);
#pragma unroll
        for (int j = 0; j < HID; ++j) t[j] = fmaf(v.w, wr[3 * HID + j], t[j]);
    }

    // ---- s = sum relu(hidF[fi] + t) over incoming edges ----
    float s[HID];
#pragma unroll
    for (int j = 0; j < HID; ++j) s[j] = 0.f;

    const int beg = g_rowptr[side * (NUM_CN + 1) + n];
    const int end = g_rowptr[side * (NUM_CN + 1) + n + 1];
    const float* hidF = g_hidF + ((size_t)side * NB + b) * NUM_VN * HID;
    const int* src = g_src + (size_t)side * NE;

    for (int e = beg; e < end; ++e) {
        int fi = src[e];
        const float4* F = reinterpret_cast<const float4*>(hidF + (size_t)fi * HID);
#pragma unroll
        for (int g = 0; g < 10; ++g) {
            float4 f = F[g];
            s[4*g+0] += fmaxf(f.x + t[4*g+0], 0.f);
            s[4*g+1] += fmaxf(f.y + t[4*g+1], 0.f);
            s[4*g+2] += fmaxf(f.z + t[4*g+2], 0.f);
            s[4*g+3] += fmaxf(f.w + t[4*g+3], 0.f);
        }
    }

    // ---- hid = s @ Wf + row @ We1[20:52] + logit * We1[52] ----
    float hid[HID];
    {
        float lg = logit[(size_t)b * NUM_CN + n];
#pragma unroll
        for (int j = 0; j < HID; ++j) hid[j] = lg * we1l[j];
    }
#pragma unroll
    for (int i = 0; i < 8; ++i) {
        float4 v = row[i];
        const float* wr = &we1h[i * 4 * HID];
#pragma unroll
        for (int j = 0; j < HID; ++j) hid[j] = fmaf(v.x, wr[j], hid[j]);
#pragma unroll
        for (int j = 0; j < HID; ++j) hid[j] = fmaf(v.y, wr[HID + j], hid[j]);
#pragma unroll
        for (int j = 0; j < HID; ++j) hid[j] = fmaf(v.z, wr[2 * HID + j], hid[j]);
#pragma unroll
        for (int j = 0; j < HID; ++j) hid[j] = fmaf(v.w, wr[3 * HID + j], hid[j]);
    }
#pragma unroll 4
    for (int i = 0; i < HID; ++i) {
        float sv = s[i];
        const float* wr = &wfs[i * HID];
#pragma unroll
        for (int j = 0; j < HID; ++j) hid[j] = fmaf(sv, wr[j], hid[j]);
    }

    // ---- out = relu(hid) @ We2 ----
    float acc[DD];
#pragma unroll
    for (int o = 0; o < DD; ++o) acc[o] = 0.f;
#pragma unroll 4
    for (int j = 0; j < HID; ++j) {
        float h = fmaxf(hid[j], 0.f);
        const float* wr = &we2s[j * DD];
#pragma unroll
        for (int o = 0; o < DD; ++o) acc[o] = fmaf(h, wr[o], acc[o]);
    }

    float* dst = out + (((size_t)side * NB + b) * NUM_CN + n) * DD;
#pragma unroll
    for (int i = 0; i < 8; ++i)
        *reinterpret_cast<float4*>(dst + 4 * i) =
            make_float4(acc[4*i], acc[4*i+1], acc[4*i+2], acc[4*i+3]);
}

extern "C" void kernel_launch(void* const* d_in, const int* in_sizes, int n_in,
                              void* d_out, int out_size)
{
    const float* h_from   = (const float*)d_in[0];
    const float* h_to_x   = (const float*)d_in[1];
    const float* h_to_z   = (const float*)d_in[2];
    const float* hx_logit = (const float*)d_in[3];
    const float* hz_logit = (const float*)d_in[4];
    const int*   fx       = (const int*)d_in[5];
    const int*   tx       = (const int*)d_in[6];
    const int*   fz       = (const int*)d_in[7];
    const int*   tz       = (const int*)d_in[8];
    const float* Wm1x     = (const float*)d_in[9];
    const float* Wm2x     = (const float*)d_in[10];
    const float* Wm1z     = (const float*)d_in[11];
    const float* Wm2z     = (const float*)d_in[12];
    const float* We1x     = (const float*)d_in[13];
    const float* We2x     = (const float*)d_in[14];
    const float* We1z     = (const float*)d_in[15];
    const float* We2z     = (const float*)d_in[16];
    float* out = (float*)d_out;

    // CSR build
    zero_cnt_kernel<<<(2 * NUM_CN + 255) / 256, 256>>>();
    dim3 hgrid(NE / 256, 2);
    hist_kernel<<<hgrid, 256>>>(tx, tz);
    scan_kernel<<<2, 1024>>>();
    fill_kernel<<<hgrid, 256>>>(fx, tx, fz, tz);

    // folded weights
    wf_build_kernel<<<2, 256>>>(Wm2x, We1x, Wm2z, We1z);

    // from-node projections
    dim3 pgrid(NUM_VN / 256, NB, 2);
    proj_from_kernel<<<pgrid, 128>>>(h_from, Wm1x, Wm1z);

    // fused edge-gather + node update
    dim3 ngrid(NUM_CN / 128, NB, 2);
    fused_node_kernel<<<ngrid, 128>>>(h_to_x, h_to_z, hx_logit, hz_logit,
                                      Wm1x, Wm1z, We1x, We1z, We2x, We2z, out);
}

// round 5
// speedup vs baseline: 2.1279x; 1.0741x over previous
#include <cuda_runtime.h>
#include <cstdint>

#define NB      4
#define NUM_VN  65536
#define NUM_CN  32768
#define DD      32
#define NE      262144
#define HID     40
#define MSG     20

// Scratch
__device__ float g_hidF[2u * NB * NUM_VN * HID];   // 84 MB from-node projections
__device__ float g_T[2u * NB * NUM_CN * HID];      // 42 MB: t = row @ Wm1[32:64]
__device__ float g_base[2u * NB * NUM_CN * HID];   // 42 MB: base = row@We1[20:52]+lg*We1[52]
__device__ int   g_cnt[2 * NUM_CN];
__device__ int   g_cur[2 * NUM_CN];
__device__ int   g_rowptr[2 * (NUM_CN + 1)];
__device__ int   g_src[2 * NE];
__device__ float g_wf[2 * HID * HID];              // Wf = Wm2 @ We1[0:MSG]

// ---------------------------------------------------------------------------
__global__ void __launch_bounds__(256) zero_cnt_kernel() {
    int i = blockIdx.x * 256 + threadIdx.x;
    if (i < 2 * NUM_CN) g_cnt[i] = 0;
}

__global__ void __launch_bounds__(256) hist_kernel(
    const int* __restrict__ tx, const int* __restrict__ tz)
{
    const int side = blockIdx.y;
    const int* ti_arr = side ? tz : tx;
    int e = blockIdx.x * 256 + threadIdx.x;
    atomicAdd(&g_cnt[side * NUM_CN + ti_arr[e]], 1);
}

__global__ void __launch_bounds__(1024) scan_kernel() {
    const int side = blockIdx.x;
    const int t = threadIdx.x;
    __shared__ int part[1024];

    const int n0 = t * 32;
    int tsum = 0;
    int loc[32];
#pragma unroll
    for (int i = 0; i < 32; ++i) { loc[i] = g_cnt[side * NUM_CN + n0 + i]; tsum += loc[i]; }
    part[t] = tsum;
    __syncthreads();
#pragma unroll
    for (int off = 1; off < 1024; off <<= 1) {
        int v = (t >= off) ? part[t - off] : 0;
        __syncthreads();
        part[t] += v;
        __syncthreads();
    }
    int base = part[t] - tsum;
#pragma unroll
    for (int i = 0; i < 32; ++i) {
        g_rowptr[side * (NUM_CN + 1) + n0 + i] = base;
        g_cur[side * NUM_CN + n0 + i] = base;
        base += loc[i];
    }
    if (t == 1023) g_rowptr[side * (NUM_CN + 1) + NUM_CN] = NE;
}

__global__ void __launch_bounds__(256) fill_kernel(
    const int* __restrict__ fx, const int* __restrict__ tx,
    const int* __restrict__ fz, const int* __restrict__ tz)
{
    const int side = blockIdx.y;
    const int* fi_arr = side ? fz : fx;
    const int* ti_arr = side ? tz : tx;
    int e = blockIdx.x * 256 + threadIdx.x;
    int ti = ti_arr[e];
    int pos = atomicAdd(&g_cur[side * NUM_CN + ti], 1);
    g_src[side * NE + pos] = fi_arr[e];
}

// Wf[i][j] = sum_k Wm2[i][k] * We1[k][j]
__global__ void __launch_bounds__(256) wf_build_kernel(
    const float* __restrict__ Wm2x, const float* __restrict__ We1x,
    const float* __restrict__ Wm2z, const float* __restrict__ We1z)
{
    const int side = blockIdx.x;
    const float* W2 = side ? Wm2z : Wm2x;
    const float* W1 = side ? We1z : We1x;
    for (int idx = threadIdx.x; idx < HID * HID; idx += 256) {
        int i = idx / HID, j = idx % HID;
        float a = 0.f;
#pragma unroll
        for (int k = 0; k < MSG; ++k) a = fmaf(W2[i * MSG + k], W1[k * HID + j], a);
        g_wf[side * HID * HID + idx] = a;
    }
}

// ---------------------------------------------------------------------------
// From-node projection, chunked outputs: hidF[side][b][vn][:] = x @ Wm1[0:32]
// Peak live: x(32) + acc(8) -> no spills.
// ---------------------------------------------------------------------------
__global__ void __launch_bounds__(256, 2) proj_from_kernel(
    const float* __restrict__ h_from,
    const float* __restrict__ Wm1x, const float* __restrict__ Wm1z)
{
    const int side = blockIdx.z;
    const int b = blockIdx.y;
    const float* __restrict__ W1 = side ? Wm1z : Wm1x;

    __shared__ float w1s[DD * HID];   // row-major [in][out]
    for (int i = threadIdx.x; i < DD * HID; i += 256) w1s[i] = W1[i];
    __syncthreads();

    const int n = blockIdx.x * 256 + threadIdx.x;

    float x[DD];
    {
        const float4* r = reinterpret_cast<const float4*>(h_from + ((size_t)b * NUM_VN + n) * DD);
#pragma unroll
        for (int i = 0; i < 8; ++i) {
            float4 v = r[i];
            x[4*i] = v.x; x[4*i+1] = v.y; x[4*i+2] = v.z; x[4*i+3] = v.w;
        }
    }

    float* dst = g_hidF + (((size_t)side * NB + b) * NUM_VN + n) * HID;
#pragma unroll
    for (int jc = 0; jc < HID / 8; ++jc) {
        float acc[8];
#pragma unroll
        for (int k = 0; k < 8; ++k) acc[k] = 0.f;
#pragma unroll
        for (int i = 0; i < DD; ++i) {
            const float* wr = &w1s[i * HID + jc * 8];
#pragma unroll
            for (int k = 0; k < 8; ++k) acc[k] = fmaf(x[i], wr[k], acc[k]);
        }
        *reinterpret_cast<float4*>(dst + jc * 8)     = make_float4(acc[0], acc[1], acc[2], acc[3]);
        *reinterpret_cast<float4*>(dst + jc * 8 + 4) = make_float4(acc[4], acc[5], acc[6], acc[7]);
    }
}

// ---------------------------------------------------------------------------
// To-node precompute: per (side, b, cn):
//   t    = row @ Wm1[32:64]
//   base = row @ We1[20:52] + logit * We1[52]
// Chunked outputs; peak live x(32)+acc(8).
// ---------------------------------------------------------------------------
__global__ void __launch_bounds__(256, 2) pre_to_kernel(
    const float* __restrict__ h_to_x, const float* __restrict__ h_to_z,
    const float* __restrict__ lx, const float* __restrict__ lz,
    const float* __restrict__ Wm1x, const float* __restrict__ Wm1z,
    const float* __restrict__ We1x, const float* __restrict__ We1z)
{
    const int side = blockIdx.z;
    const int b = blockIdx.y;
    const float* __restrict__ h_to  = side ? h_to_z : h_to_x;
    const float* __restrict__ logit = side ? lz : lx;
    const float* __restrict__ Wm1 = side ? Wm1z : Wm1x;
    const float* __restrict__ We1 = side ? We1z : We1x;

    __shared__ float wts[DD * HID];   // Wm1 rows 32..63
    __shared__ float wes[DD * HID];   // We1 rows 20..51
    __shared__ float wls[HID];        // We1 row 52
    for (int i = threadIdx.x; i < DD * HID; i += 256) wts[i] = Wm1[DD * HID + i];
    for (int i = threadIdx.x; i < DD * HID; i += 256) wes[i] = We1[MSG * HID + i];
    for (int i = threadIdx.x; i < HID; i += 256) wls[i] = We1[52 * HID + i];
    __syncthreads();

    const int n = blockIdx.x * 256 + threadIdx.x;

    float x[DD];
    {
        const float4* r = reinterpret_cast<const float4*>(h_to + ((size_t)b * NUM_CN + n) * DD);
#pragma unroll
        for (int i = 0; i < 8; ++i) {
            float4 v = r[i];
            x[4*i] = v.x; x[4*i+1] = v.y; x[4*i+2] = v.z; x[4*i+3] = v.w;
        }
    }
    const float lg = logit[(size_t)b * NUM_CN + n];

    float* tdst = g_T    + (((size_t)side * NB + b) * NUM_CN + n) * HID;
    float* bdst = g_base + (((size_t)side * NB + b) * NUM_CN + n) * HID;

#pragma unroll
    for (int jc = 0; jc < HID / 8; ++jc) {
        float acc[8];
#pragma unroll
        for (int k = 0; k < 8; ++k) acc[k] = 0.f;
#pragma unroll
        for (int i = 0; i < DD; ++i) {
            const float* wr = &wts[i * HID + jc * 8];
#pragma unroll
            for (int k = 0; k < 8; ++k) acc[k] = fmaf(x[i], wr[k], acc[k]);
        }
        *reinterpret_cast<float4*>(tdst + jc * 8)     = make_float4(acc[0], acc[1], acc[2], acc[3]);
        *reinterpret_cast<float4*>(tdst + jc * 8 + 4) = make_float4(acc[4], acc[5], acc[6], acc[7]);
    }
#pragma unroll
    for (int jc = 0; jc < HID / 8; ++jc) {
        float acc[8];
#pragma unroll
        for (int k = 0; k < 8; ++k) acc[k] = lg * wls[jc * 8 + k];
#pragma unroll
        for (int i = 0; i < DD; ++i) {
            const float* wr = &wes[i * HID + jc * 8];
#pragma unroll
            for (int k = 0; k < 8; ++k) acc[k] = fmaf(x[i], wr[k], acc[k]);
        }
        *reinterpret_cast<float4*>(bdst + jc * 8)     = make_float4(acc[0], acc[1], acc[2], acc[3]);
        *reinterpret_cast<float4*>(bdst + jc * 8 + 4) = make_float4(acc[4], acc[5], acc[6], acc[7]);
    }
}

// ---------------------------------------------------------------------------
// Fused gather + node MLP: per (side, b, cn):
//   s   = sum_e relu(hidF[fi_e] + t)          (t loaded from g_T)
//   hid = s @ Wf + base                        (base loaded chunk-wise)
//   out = relu(hid) @ We2
// ---------------------------------------------------------------------------
__global__ void __launch_bounds__(256, 2) fused_node_kernel(
    const float* __restrict__ We2x, const float* __restrict__ We2z,
    float* __restrict__ out)
{
    const int side = blockIdx.z;
    const int b = blockIdx.y;
    const float* __restrict__ We2 = side ? We2z : We2x;

    __shared__ float wfs[HID * HID];   // [in][out]
    __shared__ float we2s[HID * DD];   // [in][out]
    for (int i = threadIdx.x; i < HID * HID; i += 256) wfs[i] = g_wf[side * HID * HID + i];
    for (int i = threadIdx.x; i < HID * DD; i += 256) we2s[i] = We2[i];
    __syncthreads();

    const int n = blockIdx.x * 256 + threadIdx.x;

    // load t
    float t[HID];
    {
        const float4* r = reinterpret_cast<const float4*>(
            g_T + (((size_t)side * NB + b) * NUM_CN + n) * HID);
#pragma unroll
        for (int i = 0; i < 10; ++i) {
            float4 v = r[i];
            t[4*i] = v.x; t[4*i+1] = v.y; t[4*i+2] = v.z; t[4*i+3] = v.w;
        }
    }

    // gather-sum over incoming edges (prefetch next src index)
    float s[HID];
#pragma unroll
    for (int j = 0; j < HID; ++j) s[j] = 0.f;

    const int beg = g_rowptr[side * (NUM_CN + 1) + n];
    const int end = g_rowptr[side * (NUM_CN + 1) + n + 1];
    const float* hidF = g_hidF + ((size_t)side * NB + b) * NUM_VN * HID;
    const int* src = g_src + (size_t)side * NE;

    int fi = (beg < end) ? src[beg] : 0;
    for (int e = beg; e < end; ++e) {
        const float4* F = reinterpret_cast<const float4*>(hidF + (size_t)fi * HID);
        int fi_next = (e + 1 < end) ? src[e + 1] : 0;
        float4 f0 = F[0], f1 = F[1], f2 = F[2], f3 = F[3], f4 = F[4];
        float4 f5 = F[5], f6 = F[6], f7 = F[7], f8 = F[8], f9 = F[9];
        fi = fi_next;
        float4 fr[10] = {f0,f1,f2,f3,f4,f5,f6,f7,f8,f9};
#pragma unroll
        for (int g = 0; g < 10; ++g) {
            s[4*g+0] += fmaxf(fr[g].x + t[4*g+0], 0.f);
            s[4*g+1] += fmaxf(fr[g].y + t[4*g+1], 0.f);
            s[4*g+2] += fmaxf(fr[g].z + t[4*g+2], 0.f);
            s[4*g+3] += fmaxf(fr[g].w + t[4*g+3], 0.f);
        }
    }

    // hid = s @ Wf + base, computed chunk-wise into hid[40]
    const float* brow = g_base + (((size_t)side * NB + b) * NUM_CN + n) * HID;
    float hid[HID];
#pragma unroll
    for (int jc = 0; jc < HID / 8; ++jc) {
        float acc[8];
        float4 b0 = *reinterpret_cast<const float4*>(brow + jc * 8);
        float4 b1 = *reinterpret_cast<const float4*>(brow + jc * 8 + 4);
        acc[0] = b0.x; acc[1] = b0.y; acc[2] = b0.z; acc[3] = b0.w;
        acc[4] = b1.x; acc[5] = b1.y; acc[6] = b1.z; acc[7] = b1.w;
#pragma unroll
        for (int i = 0; i < HID; ++i) {
            const float* wr = &wfs[i * HID + jc * 8];
#pragma unroll
            for (int k = 0; k < 8; ++k) acc[k] = fmaf(s[i], wr[k], acc[k]);
        }
#pragma unroll
        for (int k = 0; k < 8; ++k) hid[jc * 8 + k] = fmaxf(acc[k], 0.f);
    }

    // out = hid @ We2
    float* dst = out + (((size_t)side * NB + b) * NUM_CN + n) * DD;
#pragma unroll
    for (int oc = 0; oc < DD / 8; ++oc) {
        float acc[8];
#pragma unroll
        for (int k = 0; k < 8; ++k) acc[k] = 0.f;
#pragma unroll
        for (int j = 0; j < HID; ++j) {
            const float* wr = &we2s[j * DD + oc * 8];
#pragma unroll
            for (int k = 0; k < 8; ++k) acc[k] = fmaf(hid[j], wr[k], acc[k]);
        }
        *reinterpret_cast<float4*>(dst + oc * 8)     = make_float4(acc[0], acc[1], acc[2], acc[3]);
        *reinterpret_cast<float4*>(dst + oc * 8 + 4) = make_float4(acc[4], acc[5], acc[6], acc[7]);
    }
}

extern "C" void kernel_launch(void* const* d_in, const int* in_sizes, int n_in,
                              void* d_out, int out_size)
{
    const float* h_from   = (const float*)d_in[0];
    const float* h_to_x   = (const float*)d_in[1];
    const float* h_to_z   = (const float*)d_in[2];
    const float* hx_logit = (const float*)d_in[3];
    const float* hz_logit = (const float*)d_in[4];
    const int*   fx       = (const int*)d_in[5];
    const int*   tx       = (const int*)d_in[6];
    const int*   fz       = (const int*)d_in[7];
    const int*   tz       = (const int*)d_in[8];
    const float* Wm1x     = (const float*)d_in[9];
    const float* Wm2x     = (const float*)d_in[10];
    const float* Wm1z     = (const float*)d_in[11];
    const float* Wm2z     = (const float*)d_in[12];
    const float* We1x     = (const float*)d_in[13];
    const float* We2x     = (const float*)d_in[14];
    const float* We1z     = (const float*)d_in[15];
    const float* We2z     = (const float*)d_in[16];
    float* out = (float*)d_out;

    // CSR build
    zero_cnt_kernel<<<(2 * NUM_CN + 255) / 256, 256>>>();
    dim3 hgrid(NE / 256, 2);
    hist_kernel<<<hgrid, 256>>>(tx, tz);
    scan_kernel<<<2, 1024>>>();
    fill_kernel<<<hgrid, 256>>>(fx, tx, fz, tz);

    // folded weights
    wf_build_kernel<<<2, 256>>>(Wm2x, We1x, Wm2z, We1z);

    // projections / precompute
    dim3 pgrid(NUM_VN / 256, NB, 2);
    proj_from_kernel<<<pgrid, 256>>>(h_from, Wm1x, Wm1z);

    dim3 tgrid(NUM_CN / 256, NB, 2);
    pre_to_kernel<<<tgrid, 256>>>(h_to_x, h_to_z, hx_logit, hz_logit,
                                  Wm1x, Wm1z, We1x, We1z);

    // fused gather + node MLP
    fused_node_kernel<<<tgrid, 256>>>(We2x, We2z, out);
}